// round 1
// baseline (speedup 1.0000x reference)
#include <cuda_runtime.h>
#include <cuda_bf16.h>

// Problem constants (fixed by dataset)
#define D_MODEL 1024
#define ADAPT   128
#define NUM_LIB 8
#define NPAIR   (NUM_LIB * NUM_LIB)   // 64
#define MAXB    1024

// Device scratch (no allocations allowed)
__device__ int   g_off[NPAIR + 1];
__device__ int   g_rows[MAXB];
__device__ float g_h[MAXB * ADAPT];

// ---------------------------------------------------------------------------
// Build per-pair CSR of row indices. One CTA, 1024 threads.
// ---------------------------------------------------------------------------
__global__ void k_build(const int* __restrict__ src, const int* __restrict__ tgt, int B) {
    __shared__ int cnt[NPAIR];
    __shared__ int off[NPAIR + 1];
    int t = threadIdx.x;
    if (t < NPAIR) cnt[t] = 0;
    __syncthreads();
    int p = -1, slot = 0;
    if (t < B) {
        int s = src[t], g = tgt[t];
        if (s != g) {
            p = s * NUM_LIB + g;
            slot = atomicAdd(&cnt[p], 1);
        }
    }
    __syncthreads();
    if (t == 0) {
        int acc = 0;
        for (int i = 0; i < NPAIR; i++) { off[i] = acc; acc += cnt[i]; }
        off[NPAIR] = acc;
    }
    __syncthreads();
    if (t <= NPAIR) g_off[t] = off[t];
    if (p >= 0) g_rows[off[p] + slot] = t;
}

// ---------------------------------------------------------------------------
// Identity rows: out[b] = x[b]
// ---------------------------------------------------------------------------
__global__ void k_copy(const float* __restrict__ x,
                       const int* __restrict__ src, const int* __restrict__ tgt,
                       float* __restrict__ out) {
    int b = blockIdx.x;
    if (src[b] != tgt[b]) return;
    const float4* xi = (const float4*)(x + (size_t)b * D_MODEL);
    float4* yo = (float4*)(out + (size_t)b * D_MODEL);
    for (int i = threadIdx.x; i < D_MODEL / 4; i += blockDim.x) yo[i] = xi[i];
}

// ---------------------------------------------------------------------------
// GEMM1: g_h[row, a] = relu( x[row,:] . W1[p,:,a] + b1[p,a] )
// grid (NPAIR, 4), 256 threads. 8 rows per chunk.
// smem: xs[8][1024] (32 KB) + ws[64][128] (32 KB) = 64 KB dynamic.
// ---------------------------------------------------------------------------
#define G1_ROWS 8
#define G1_KB   64
#define G1_SMEM ((G1_ROWS * D_MODEL + G1_KB * ADAPT) * 4)

__global__ void __launch_bounds__(256, 1)
k_gemm1(const float* __restrict__ x, const float* __restrict__ W1,
        const float* __restrict__ b1) {
    extern __shared__ float sm[];
    float* xs = sm;                       // [8][1024]
    float* ws = sm + G1_ROWS * D_MODEL;   // [64][128]

    int p = blockIdx.x;
    int begin = g_off[p], end = g_off[p + 1];
    int t = threadIdx.x;
    int a = t & (ADAPT - 1);
    int half = t >> 7;                    // 0/1 -> rows [half*4, half*4+4)
    float bias = b1[p * ADAPT + a];
    const float* Wp = W1 + (size_t)p * D_MODEL * ADAPT;

    for (int base = begin + blockIdx.y * G1_ROWS; base < end; base += gridDim.y * G1_ROWS) {
        int nrows = min(G1_ROWS, end - base);
        __syncthreads();  // previous iteration's reads of xs done
        // Gather x rows into smem (zero-pad missing rows)
        for (int i = t; i < G1_ROWS * (D_MODEL / 4); i += 256) {
            int r = i >> 8;               // 256 float4 per row
            int c = i & 255;
            float4 v = make_float4(0.f, 0.f, 0.f, 0.f);
            if (r < nrows) {
                int row = g_rows[base + r];
                v = ((const float4*)(x + (size_t)row * D_MODEL))[c];
            }
            ((float4*)xs)[i] = v;
        }

        float acc[4] = {0.f, 0.f, 0.f, 0.f};
        for (int k0 = 0; k0 < D_MODEL; k0 += G1_KB) {
            __syncthreads();              // done reading previous ws / xs staged
            const float4* Wg4 = (const float4*)(Wp + (size_t)k0 * ADAPT);
            for (int i = t; i < G1_KB * ADAPT / 4; i += 256)
                ((float4*)ws)[i] = Wg4[i];
            __syncthreads();
            #pragma unroll 8
            for (int kk = 0; kk < G1_KB; kk += 4) {
                float w0 = ws[(kk + 0) * ADAPT + a];
                float w1 = ws[(kk + 1) * ADAPT + a];
                float w2 = ws[(kk + 2) * ADAPT + a];
                float w3 = ws[(kk + 3) * ADAPT + a];
                #pragma unroll
                for (int j = 0; j < 4; j++) {
                    float4 xv = *(const float4*)(xs + (half * 4 + j) * D_MODEL + k0 + kk);
                    acc[j] = fmaf(xv.x, w0, acc[j]);
                    acc[j] = fmaf(xv.y, w1, acc[j]);
                    acc[j] = fmaf(xv.z, w2, acc[j]);
                    acc[j] = fmaf(xv.w, w3, acc[j]);
                }
            }
        }
        #pragma unroll
        for (int j = 0; j < 4; j++) {
            int r = half * 4 + j;
            if (r < nrows)
                g_h[(size_t)g_rows[base + r] * ADAPT + a] = fmaxf(acc[j] + bias, 0.f);
        }
    }
}

// ---------------------------------------------------------------------------
// GEMM2: out[row, d] = g_h[row,:] . W2[p,:,d] + b2[p,d]
// grid (NPAIR, 4 d-chunks of 256), 256 threads; each thread owns one d.
// smem: ws[128][256] (128 KB) + hs[16][128] (8 KB) = 136 KB dynamic.
// ---------------------------------------------------------------------------
#define G2_ROWS 16
#define G2_DC   256
#define G2_SMEM ((ADAPT * G2_DC + G2_ROWS * ADAPT) * 4)

__global__ void __launch_bounds__(256, 1)
k_gemm2(const float* __restrict__ W2, const float* __restrict__ b2,
        float* __restrict__ out) {
    extern __shared__ float sm[];
    float* ws = sm;                   // [128][256]
    float* hs = sm + ADAPT * G2_DC;   // [16][128]

    int p = blockIdx.x;
    int begin = g_off[p], end = g_off[p + 1];
    if (begin == end) return;
    int t = threadIdx.x;
    int dc = blockIdx.y;
    int d = dc * G2_DC + t;

    // Stage W2 slab for this (pair, d-chunk) once: 128 x 256 floats
    const float* Wp = W2 + (size_t)p * ADAPT * D_MODEL + dc * G2_DC;
    for (int i = t; i < ADAPT * G2_DC / 4; i += 256) {
        int aa = i >> 6;              // 64 float4 per a-row
        int c  = i & 63;
        ((float4*)ws)[i] = *(const float4*)(Wp + (size_t)aa * D_MODEL + c * 4);
    }
    float bias = b2[(size_t)p * D_MODEL + d];

    for (int base = begin; base < end; base += G2_ROWS) {
        int nrows = min(G2_ROWS, end - base);
        __syncthreads();              // ws staged / previous hs reads done
        for (int i = t; i < G2_ROWS * ADAPT / 4; i += 256) {
            int r = i >> 5;           // 32 float4 per row
            int c = i & 31;
            float4 v = make_float4(0.f, 0.f, 0.f, 0.f);
            if (r < nrows)
                v = *(const float4*)(g_h + (size_t)g_rows[base + r] * ADAPT + c * 4);
            ((float4*)hs)[i] = v;
        }
        __syncthreads();

        float acc[G2_ROWS];
        #pragma unroll
        for (int r = 0; r < G2_ROWS; r++) acc[r] = 0.f;

        #pragma unroll 4
        for (int aa = 0; aa < ADAPT; aa += 4) {
            float w0 = ws[(aa + 0) * G2_DC + t];
            float w1 = ws[(aa + 1) * G2_DC + t];
            float w2 = ws[(aa + 2) * G2_DC + t];
            float w3 = ws[(aa + 3) * G2_DC + t];
            #pragma unroll
            for (int r = 0; r < G2_ROWS; r++) {
                float4 hv = *(const float4*)(hs + r * ADAPT + aa);
                acc[r] = fmaf(hv.x, w0, acc[r]);
                acc[r] = fmaf(hv.y, w1, acc[r]);
                acc[r] = fmaf(hv.z, w2, acc[r]);
                acc[r] = fmaf(hv.w, w3, acc[r]);
            }
        }
        #pragma unroll
        for (int r = 0; r < G2_ROWS; r++) {
            if (r < nrows)
                out[(size_t)g_rows[base + r] * D_MODEL + d] = acc[r] + bias;
        }
    }
}

// ---------------------------------------------------------------------------
extern "C" void kernel_launch(void* const* d_in, const int* in_sizes, int n_in,
                              void* d_out, int out_size) {
    const float* x   = (const float*)d_in[0];
    const int*   src = (const int*)d_in[1];
    const int*   tgt = (const int*)d_in[2];
    const float* W1  = (const float*)d_in[3];
    const float* b1  = (const float*)d_in[4];
    const float* W2  = (const float*)d_in[5];
    const float* b2  = (const float*)d_in[6];
    float* out = (float*)d_out;
    int B = in_sizes[1];  // 1024

    cudaFuncSetAttribute(k_gemm1, cudaFuncAttributeMaxDynamicSharedMemorySize, G1_SMEM);
    cudaFuncSetAttribute(k_gemm2, cudaFuncAttributeMaxDynamicSharedMemorySize, G2_SMEM);

    k_build<<<1, 1024>>>(src, tgt, B);
    k_copy<<<B, 128>>>(x, src, tgt, out);
    k_gemm1<<<dim3(NPAIR, 4), 256, G1_SMEM>>>(x, W1, b1);
    k_gemm2<<<dim3(NPAIR, 4), 256, G2_SMEM>>>(W2, b2, out);
}

// round 2
// speedup vs baseline: 1.4488x; 1.4488x over previous
#include <cuda_runtime.h>

// Problem constants (fixed by dataset)
#define D_MODEL 1024
#define ADAPT   128
#define NUM_LIB 8
#define NPAIR   (NUM_LIB * NUM_LIB)   // 64
#define MAXB    1024
#define KC      4                      // K-split for gemm1
#define KCH     (D_MODEL / KC)         // 256
#define NDC     8                      // D-split for gemm2 (128 cols each)
#define RT      8                      // row tile

// Device scratch (no allocations allowed)
__device__ int   g_off[NPAIR + 1];
__device__ int   g_rows[MAXB];
__device__ float g_hp[KC][MAXB * ADAPT];   // partial pre-activation sums

// ---------------------------------------------------------------------------
// Build per-pair CSR of row indices. One CTA, 1024 threads.
// ---------------------------------------------------------------------------
__global__ void k_build(const int* __restrict__ src, const int* __restrict__ tgt, int B) {
    __shared__ int cnt[NPAIR];
    __shared__ int off[NPAIR + 1];
    int t = threadIdx.x;
    if (t < NPAIR) cnt[t] = 0;
    __syncthreads();
    int p = -1, slot = 0;
    if (t < B) {
        int s = src[t], g = tgt[t];
        if (s != g) {
            p = s * NUM_LIB + g;
            slot = atomicAdd(&cnt[p], 1);
        }
    }
    __syncthreads();
    if (t == 0) {
        int acc = 0;
        for (int i = 0; i < NPAIR; i++) { off[i] = acc; acc += cnt[i]; }
        off[NPAIR] = acc;
    }
    __syncthreads();
    if (t <= NPAIR) g_off[t] = off[t];
    if (p >= 0) g_rows[off[p] + slot] = t;
}

// ---------------------------------------------------------------------------
// Identity rows: out[b] = x[b]
// ---------------------------------------------------------------------------
__global__ void k_copy(const float* __restrict__ x,
                       const int* __restrict__ src, const int* __restrict__ tgt,
                       float* __restrict__ out) {
    int b = blockIdx.x;
    if (src[b] != tgt[b]) return;
    const float4* xi = (const float4*)(x + (size_t)b * D_MODEL);
    float4* yo = (float4*)(out + (size_t)b * D_MODEL);
    #pragma unroll
    for (int i = threadIdx.x; i < D_MODEL / 4; i += 128) yo[i] = xi[i];
}

// ---------------------------------------------------------------------------
// GEMM1 (K-split partials): g_hp[kz][row, a] = x[row, kz*256:+256] . W1[p, same, a]
// grid (NPAIR, KC, 3), 128 threads. Thread t owns column a=t, acc over 8 rows.
// W1 streamed from gmem (coalesced); x rows broadcast from smem.
// ---------------------------------------------------------------------------
__global__ void __launch_bounds__(128, 6)
k_gemm1(const float* __restrict__ x, const float* __restrict__ W1) {
    __shared__ float xs[RT * KCH];       // 8 KB
    int p  = blockIdx.x;
    int kz = blockIdx.y;
    int begin = g_off[p], end = g_off[p + 1];
    int t = threadIdx.x;                 // a column
    const float* Wp = W1 + ((size_t)p * D_MODEL + (size_t)kz * KCH) * ADAPT;
    float* hp = g_hp[kz];

    for (int base = begin + blockIdx.z * RT; base < end; base += gridDim.z * RT) {
        int n = min(RT, end - base);
        __syncthreads();                 // previous iteration done with xs
        // stage x rows [base, base+n), k-slice [kz*KCH, +KCH), zero-pad
        for (int i = t; i < RT * (KCH / 4); i += 128) {
            int r = i >> 6;              // 64 float4 per row
            int c = i & 63;
            float4 v = make_float4(0.f, 0.f, 0.f, 0.f);
            if (r < n)
                v = ((const float4*)(x + (size_t)g_rows[base + r] * D_MODEL + kz * KCH))[c];
            ((float4*)xs)[i] = v;
        }
        __syncthreads();

        float acc[RT];
        #pragma unroll
        for (int r = 0; r < RT; r++) acc[r] = 0.f;

        #pragma unroll 2
        for (int k = 0; k < KCH; k += 4) {
            float w0 = __ldg(Wp + (size_t)(k + 0) * ADAPT + t);
            float w1 = __ldg(Wp + (size_t)(k + 1) * ADAPT + t);
            float w2 = __ldg(Wp + (size_t)(k + 2) * ADAPT + t);
            float w3 = __ldg(Wp + (size_t)(k + 3) * ADAPT + t);
            #pragma unroll
            for (int r = 0; r < RT; r++) {
                float4 xv = *(const float4*)(xs + r * KCH + k);
                acc[r] = fmaf(xv.x, w0, acc[r]);
                acc[r] = fmaf(xv.y, w1, acc[r]);
                acc[r] = fmaf(xv.z, w2, acc[r]);
                acc[r] = fmaf(xv.w, w3, acc[r]);
            }
        }
        #pragma unroll
        for (int r = 0; r < RT; r++)
            if (r < n)
                hp[(size_t)g_rows[base + r] * ADAPT + t] = acc[r];
    }
}

// ---------------------------------------------------------------------------
// GEMM2: out[row, d] = relu(sum_kz g_hp[kz] + b1) . W2[p,:,d] + b2[p,d]
// grid (NPAIR, NDC, 2), 128 threads. Thread t owns d = dc*128+t, acc over 8 rows.
// W2 streamed from gmem (coalesced); h summed+biased+relu'd into smem broadcast.
// ---------------------------------------------------------------------------
__global__ void __launch_bounds__(128, 6)
k_gemm2(const float* __restrict__ W2, const float* __restrict__ b1,
        const float* __restrict__ b2, float* __restrict__ out) {
    __shared__ float hs[RT * ADAPT];     // 4 KB
    int p  = blockIdx.x;
    int dc = blockIdx.y;
    int begin = g_off[p], end = g_off[p + 1];
    int t = threadIdx.x;
    int d = dc * 128 + t;
    const float* Wp = W2 + (size_t)p * ADAPT * D_MODEL + d;
    float bb1 = b1[p * ADAPT + t];
    float bb2 = b2[(size_t)p * D_MODEL + d];

    for (int base = begin + blockIdx.z * RT; base < end; base += gridDim.z * RT) {
        int n = min(RT, end - base);
        __syncthreads();                 // previous iteration done with hs
        // stage h = relu(sum of K-partials + b1); zero-pad missing rows
        #pragma unroll
        for (int r = 0; r < RT; r++) {
            float v = 0.f;
            if (r < n) {
                size_t idx = (size_t)g_rows[base + r] * ADAPT + t;
                v = fmaxf(g_hp[0][idx] + g_hp[1][idx] +
                          g_hp[2][idx] + g_hp[3][idx] + bb1, 0.f);
            }
            hs[r * ADAPT + t] = v;
        }
        __syncthreads();

        float acc[RT];
        #pragma unroll
        for (int r = 0; r < RT; r++) acc[r] = 0.f;

        #pragma unroll 2
        for (int aa = 0; aa < ADAPT; aa += 4) {
            float w0 = __ldg(Wp + (size_t)(aa + 0) * D_MODEL);
            float w1 = __ldg(Wp + (size_t)(aa + 1) * D_MODEL);
            float w2 = __ldg(Wp + (size_t)(aa + 2) * D_MODEL);
            float w3 = __ldg(Wp + (size_t)(aa + 3) * D_MODEL);
            #pragma unroll
            for (int r = 0; r < RT; r++) {
                float4 hv = *(const float4*)(hs + r * ADAPT + aa);
                acc[r] = fmaf(hv.x, w0, acc[r]);
                acc[r] = fmaf(hv.y, w1, acc[r]);
                acc[r] = fmaf(hv.z, w2, acc[r]);
                acc[r] = fmaf(hv.w, w3, acc[r]);
            }
        }
        #pragma unroll
        for (int r = 0; r < RT; r++)
            if (r < n)
                out[(size_t)g_rows[base + r] * D_MODEL + d] = acc[r] + bb2;
    }
}

// ---------------------------------------------------------------------------
extern "C" void kernel_launch(void* const* d_in, const int* in_sizes, int n_in,
                              void* d_out, int out_size) {
    const float* x   = (const float*)d_in[0];
    const int*   src = (const int*)d_in[1];
    const int*   tgt = (const int*)d_in[2];
    const float* W1  = (const float*)d_in[3];
    const float* b1  = (const float*)d_in[4];
    const float* W2  = (const float*)d_in[5];
    const float* b2  = (const float*)d_in[6];
    float* out = (float*)d_out;
    int B = in_sizes[1];  // 1024

    k_build<<<1, 1024>>>(src, tgt, B);
    k_copy<<<B, 128>>>(x, src, tgt, out);
    k_gemm1<<<dim3(NPAIR, KC, 3), 128>>>(x, W1);
    k_gemm2<<<dim3(NPAIR, NDC, 2), 128>>>(W2, b1, b2, out);
}